// round 17
// baseline (speedup 1.0000x reference)
#include <cuda_runtime.h>
#include <cuda_bf16.h>
#include <cuda_fp16.h>
#include <cstdint>

// ---------------------------------------------------------------------------
// BEVSampling (sm_100 baseline PTX):
//  k_transpose: NCHW fp32 -> NHWC fp16 features (+ folded w2 prep blocks)
//  k_mlp_mma:   pos-MLP fp16 mma.sync GEMM; 2 full tiles/CTA + 66 half-tiles
//  k_sample:    compact-smem variant (25.6KB: aliased scratch + half2
//               weights) at launch_bounds(256,6) -> 6 CTAs/SM AND ~74KB L1D
//               for coarse-level tap reuse.
// ---------------------------------------------------------------------------

#define NUM_CAMS 6
#define EMBED    128
#define NP       8
#define GQ       10000
#define NPTS     80000
#define FEAT_TOTAL 2872320  // 6*128*(2816+704+176+44)

__device__ __half g_feat[FEAT_TOTAL];   // ~5.7 MB NHWC fp16 scratch
__device__ __half g_w2[256 * 128];      // w2^T fp16, [n][k]

// ---------------------------------------------------------------------------
// k_transpose (+ folded w2 prep in blocks >= 2832)
// ---------------------------------------------------------------------------
__global__ __launch_bounds__(256) void k_transpose(
    const float* __restrict__ f0, const float* __restrict__ f1,
    const float* __restrict__ f2, const float* __restrict__ f3,
    const float* __restrict__ w2)
{
    __shared__ float s[32 * 33];
    int bid = blockIdx.x;
    int tx = threadIdx.x, ty = threadIdx.y;

    if (bid >= 2832) {                       // folded k_prep
        int i = (bid - 2832) * 256 + ty * 32 + tx;   // 32768 elements
        int n = i >> 8, k = i & 255;
        g_w2[n * 256 + k] = __float2half(w2[k * 128 + n]);
        return;
    }

    const float* src; int HW, ptiles, loff, tl;
    if (bid < 2112)      { src = f0; HW = 2816; ptiles = 88; loff = 0;       tl = bid; }
    else if (bid < 2640) { src = f1; HW = 704;  ptiles = 22; loff = 2162688; tl = bid - 2112; }
    else if (bid < 2784) { src = f2; HW = 176;  ptiles = 6;  loff = 2703360; tl = bid - 2640; }
    else                 { src = f3; HW = 44;   ptiles = 2;  loff = 2838528; tl = bid - 2784; }

    int per_cam = ptiles * 4;
    int cam = tl / per_cam;
    int r   = tl - cam * per_cam;
    int c0  = (r & 3) * 32;
    int p0  = (r >> 2) * 32;

    const float* sp = src + (long)cam * 128 * HW;
    #pragma unroll
    for (int j = 0; j < 4; ++j) {
        int cl = ty + j * 8;
        int p  = p0 + tx;
        float v = (p < HW) ? sp[(c0 + cl) * HW + p] : 0.f;
        s[tx * 33 + cl] = v;
    }
    __syncthreads();
    __half* dst = g_feat + loff + (long)cam * HW * 128;
    #pragma unroll
    for (int j = 0; j < 4; ++j) {
        int pl = ty + j * 8;
        int p  = p0 + pl;
        if (p < HW) dst[p * 128 + c0 + tx] = __float2half(s[pl * 33 + tx]);
    }
}

// ---------------------------------------------------------------------------
__device__ __forceinline__ uint32_t smem_u32(const void* p) {
    return (uint32_t)__cvta_generic_to_shared(p);
}
__device__ __forceinline__ void ldsm_x4(uint32_t* r, uint32_t addr) {
    asm volatile(
        "ldmatrix.sync.aligned.m8n8.x4.shared.b16 {%0,%1,%2,%3}, [%4];"
        : "=r"(r[0]), "=r"(r[1]), "=r"(r[2]), "=r"(r[3]) : "r"(addr));
}
__device__ __forceinline__ void mma_f16(float* d,
    uint32_t a0, uint32_t a1, uint32_t a2, uint32_t a3,
    uint32_t b0, uint32_t b1)
{
    asm volatile(
        "mma.sync.aligned.m16n8k16.row.col.f32.f16.f16.f32 "
        "{%0,%1,%2,%3}, {%4,%5,%6,%7}, {%8,%9}, {%0,%1,%2,%3};"
        : "+f"(d[0]), "+f"(d[1]), "+f"(d[2]), "+f"(d[3])
        : "r"(a0), "r"(a1), "r"(a2), "r"(a3), "r"(b0), "r"(b1));
}

// ---------------------------------------------------------------------------
// K1 (unchanged from R16): 2 full tiles per CTA + 66 half-tiles tail.
// ---------------------------------------------------------------------------
#define K1_GRID  296
#define SA 136
#define SB 264
#define SM_B2   0
#define SM_B1   512
#define SM_W1   1536
#define SM_REF  4608
#define SM_A    6144
#define SM_Bm   40960
#define K1_SMEM 108544

__global__ __launch_bounds__(256, 2) void k_mlp_mma(
    const float* __restrict__ ref,
    const float* __restrict__ w1,
    const float* __restrict__ b1,
    const float* __restrict__ b2,
    float* __restrict__ out)
{
    extern __shared__ char smb[];
    float* b2s  = (float*)(smb + SM_B2);
    float* b1s  = (float*)(smb + SM_B1);
    float* w1s  = (float*)(smb + SM_W1);
    float* refs = (float*)(smb + SM_REF);
    __half* Ah  = (__half*)(smb + SM_A);
    __half* Bh  = (__half*)(smb + SM_Bm);
    float* S    = (float*)(smb + SM_A);   // epilogue alias [c][66]

    const int t    = threadIdx.x;
    const int wid  = t >> 5;
    const int lane = t & 31;
    const int mw   = wid >> 1;
    const int nw   = (wid & 1) * 64;

    const uint32_t aBase = smem_u32(smb + SM_A);
    const uint32_t bBase = smem_u32(smb + SM_Bm);

    for (int i = t; i < 768; i += 256) w1s[i] = w1[i];
    if (t < 256) b1s[t] = b1[t];
    if (t < 128) b2s[t] = b2[t];
    for (int i = t; i < 128 * 32; i += 256) {
        int n = i >> 5, j = i & 31;
        *(uint4*)(Bh + n * SB + j * 8) = ((const uint4*)(g_w2 + n * 256))[j];
    }

    const int aRow = lane & 15;
    const int aK8  = (lane >> 4) << 3;
    const int bRow = (lane & 7) + ((lane >> 4) << 3);
    const int bK8  = ((lane >> 3) & 1) << 3;

    const int b = blockIdx.x;
    const int nunits = (b < 66) ? 3 : 2;

    for (int unit = 0; unit < nunits; ++unit) {
        int n0, rows;
        if (unit == 0)      { n0 = b * 128;            rows = 128; }
        else if (unit == 1) { n0 = (b + K1_GRID) * 128; rows = 128; }
        else                { n0 = 75776 + b * 64;      rows = 64;  }

        __syncthreads();
        for (int i = t; i < 3 * rows; i += 256) {
            int d = i / rows, r = i - d * rows;
            refs[d * 128 + r] = ref[(n0 + r) * 3 + d];
        }

        float acc[2][8][4];
        #pragma unroll
        for (int mt = 0; mt < 2; ++mt)
            #pragma unroll
            for (int nt = 0; nt < 8; ++nt)
                #pragma unroll
                for (int j = 0; j < 4; ++j) acc[mt][nt][j] = 0.f;

        for (int chunk = 0; chunk < 2; ++chunk) {
            const int kb = chunk * 128;
            __syncthreads();

            for (int i = t; i < rows * 64; i += 256) {
                int row = i >> 6, kp = i & 63;
                int k = kb + kp * 2;
                float x = refs[row], y = refs[128 + row], z = refs[256 + row];
                float h0 = fmaxf(fmaf(x, w1s[k],
                                 fmaf(y, w1s[256 + k],
                                 fmaf(z, w1s[512 + k], b1s[k]))), 0.f);
                float h1 = fmaxf(fmaf(x, w1s[k + 1],
                                 fmaf(y, w1s[256 + k + 1],
                                 fmaf(z, w1s[512 + k + 1], b1s[k + 1]))), 0.f);
                *(__half2*)(Ah + row * SA + kp * 2) = __floats2half2_rn(h0, h1);
            }
            __syncthreads();

            if (mw * 32 < rows) {
                #pragma unroll
                for (int ks = 0; ks < 8; ++ks) {
                    const int k0 = ks * 16;
                    const int kg = kb + k0;
                    uint32_t a[2][4];
                    #pragma unroll
                    for (int mt = 0; mt < 2; ++mt) {
                        uint32_t addr = aBase +
                            (((mw * 32 + mt * 16 + aRow) * SA) + k0 + aK8) * 2;
                        ldsm_x4(a[mt], addr);
                    }
                    uint32_t bfr[8][2];
                    #pragma unroll
                    for (int ntp = 0; ntp < 4; ++ntp) {
                        uint32_t addr = bBase +
                            (((nw + ntp * 16 + bRow) * SB) + kg + bK8) * 2;
                        uint32_t r[4];
                        ldsm_x4(r, addr);
                        bfr[ntp * 2][0]     = r[0];
                        bfr[ntp * 2][1]     = r[1];
                        bfr[ntp * 2 + 1][0] = r[2];
                        bfr[ntp * 2 + 1][1] = r[3];
                    }
                    #pragma unroll
                    for (int nt = 0; nt < 8; ++nt)
                        #pragma unroll
                        for (int mt = 0; mt < 2; ++mt)
                            mma_f16(acc[mt][nt], a[mt][0], a[mt][1], a[mt][2],
                                    a[mt][3], bfr[nt][0], bfr[nt][1]);
                }
            }
        }
        __syncthreads();

        if (mw < 2) {
            #pragma unroll
            for (int mt = 0; mt < 2; ++mt)
                #pragma unroll
                for (int nt = 0; nt < 8; ++nt) {
                    int r = mw * 32 + mt * 16 + (lane >> 2);
                    int c = nw + nt * 8 + (lane & 3) * 2;
                    S[c * 66 + r]           = acc[mt][nt][0];
                    S[(c + 1) * 66 + r]     = acc[mt][nt][1];
                    S[c * 66 + r + 8]       = acc[mt][nt][2];
                    S[(c + 1) * 66 + r + 8] = acc[mt][nt][3];
                }
        }
        __syncthreads();
        for (int i = t; i < 128 * 64; i += 256) {
            int c = i >> 6, m = i & 63;
            out[c * NPTS + n0 + m] = S[c * 66 + m] + b2s[c];
        }

        if (rows == 128) {
            __syncthreads();
            if (mw >= 2) {
                #pragma unroll
                for (int mt = 0; mt < 2; ++mt)
                    #pragma unroll
                    for (int nt = 0; nt < 8; ++nt) {
                        int r = (mw - 2) * 32 + mt * 16 + (lane >> 2);
                        int c = nw + nt * 8 + (lane & 3) * 2;
                        S[c * 66 + r]           = acc[mt][nt][0];
                        S[(c + 1) * 66 + r]     = acc[mt][nt][1];
                        S[c * 66 + r + 8]       = acc[mt][nt][2];
                        S[(c + 1) * 66 + r + 8] = acc[mt][nt][3];
                    }
            }
            __syncthreads();
            for (int i = t; i < 128 * 64; i += 256) {
                int c = i >> 6, m = i & 63;
                out[c * NPTS + n0 + 64 + m] = S[c * 66 + m] + b2s[c];
            }
        }
    }
}

// ---------------------------------------------------------------------------
// K2: compact smem (25.6KB: aliased phase scratch + half2 weights) at
// launch_bounds(256,6): 6 CTAs/SM by regs, ~74KB L1D for tap reuse.
// ---------------------------------------------------------------------------
__global__ __launch_bounds__(256, 6) void k_sample(
    const float* __restrict__ ref,   // [8, 10000, 3] normalized
    const float* __restrict__ l2i,   // [6,4,4]
    float* __restrict__ out)         // [128, 8, 10000]
{
    __shared__ float U[EMBED * 33];      // ph0-2 scratch, then S[c][33]
    __shared__ int   cnt[32];
    __shared__ int   entO[32 * 24];      // packed 4B codes
    __shared__ uint2 entW[32 * 24];      // 2x half2 weights

    float* refc = U;                 // [3][32]   (ph0-1)
    float* l2is = U + 96;            // 96        (ph0-1)
    float* um   = U + 192;           // [6][32]   (ph1-2)
    float* vm   = U + 384;           // [6][32]
    int*   vld  = (int*)(U + 576);   // [6][32]
    float* S    = U;                 // phase 3+

    const int t  = threadIdx.x;
    const int p  = blockIdx.y;
    const int q0 = blockIdx.x * 32;

    if (t < 96) {
        l2is[t] = l2i[t];
        int qi = t & 31, d = t >> 5;
        int q = q0 + qi;
        refc[(d << 5) + qi] = (q < GQ) ? ref[(p * GQ + q) * 3 + d] : 0.f;
    }
    __syncthreads();

    // phase 1: project
    if (t < 192) {
        int qi = t & 31, cam = t >> 5;
        float rx = refc[qi], ry = refc[32 + qi], rz = refc[64 + qi];
        float px = fmaf(rx, 100.f, -50.f);
        float py = fmaf(ry, 100.f, -50.f);
        float pz = fmaf(rz,   8.f,  -4.f);
        const float* M = &l2is[cam * 16];
        float cx = fmaf(M[0], px, fmaf(M[1],  py, fmaf(M[2],  pz, M[3])));
        float cy = fmaf(M[4], px, fmaf(M[5],  py, fmaf(M[6],  pz, M[7])));
        float cz = fmaf(M[8], px, fmaf(M[9],  py, fmaf(M[10], pz, M[11])));
        float zs = fmaxf(cz, 1e-6f);
        float u = __fdiv_rn(__fdiv_rn(cx, zs), 704.f);
        float v = __fdiv_rn(__fdiv_rn(cy, zs), 256.f);
        um[cam * 32 + qi] = u;
        vm[cam * 32 + qi] = v;
        vld[cam * 32 + qi] = (cz > 1e-6f) & (u > 0.f) & (u < 1.f)
                           & (v > 0.f) & (v < 1.f);
    }
    __syncthreads();

    // phase 2: deterministic compaction + packed tap codes
    if (t < 192) {
        int qi = t & 31, cam = t >> 5;
        if (vld[cam * 32 + qi]) {
            int rank = 0;
            for (int pc = 0; pc < cam; ++pc) rank += vld[pc * 32 + qi];
            float u = um[cam * 32 + qi];
            float v = vm[cam * 32 + qi];
            const int LW_[4]   = {88, 44, 22, 11};
            const int LH_[4]   = {32, 16, 8, 4};
            const int LHW_[4]  = {2816, 704, 176, 44};
            const int LOFF_[4] = {0, 2162688, 2703360, 2838528};
            #pragma unroll
            for (int l = 0; l < 4; ++l) {
                const int W = LW_[l], H = LH_[l];
                float x = fmaf(u, (float)W, -0.5f);
                float y = fmaf(v, (float)H, -0.5f);
                float xf = floorf(x), yf = floorf(y);
                float wx = x - xf,   wy = y - yf;
                int x0 = (int)xf, y0 = (int)yf;
                int xc0 = min(max(x0, 0), W - 1);
                int xc1 = min(max(x0 + 1, 0), W - 1);
                int yc0 = min(max(y0, 0), H - 1);
                int yc1 = min(max(y0 + 1, 0), H - 1);
                float okx0 = (x0 >= 0  && x0 < W)     ? 1.f : 0.f;
                float okx1 = (x0 >= -1 && x0 < W - 1) ? 1.f : 0.f;
                float oky0 = (y0 >= 0  && y0 < H)     ? 1.f : 0.f;
                float oky1 = (y0 >= -1 && y0 < H - 1) ? 1.f : 0.f;
                int base = LOFF_[l] + cam * (LHW_[l] << 7)
                         + ((yc0 * W + xc0) << 7);
                int code = base | (xc1 > xc0 ? 1 : 0)
                                | (yc1 > yc0 ? 2 : 0) | (l << 2);
                float w00 = (1.f - wx) * (1.f - wy) * okx0 * oky0 * 0.25f;
                float w01 = wx         * (1.f - wy) * okx1 * oky0 * 0.25f;
                float w10 = (1.f - wx) * wy         * okx0 * oky1 * 0.25f;
                float w11 = wx         * wy         * okx1 * oky1 * 0.25f;
                uint2 wp;
                *(__half2*)&wp.x = __floats2half2_rn(w00, w01);
                *(__half2*)&wp.y = __floats2half2_rn(w10, w11);
                int slot = qi * 24 + rank * 4 + l;
                entO[slot] = code;
                entW[slot] = wp;
            }
        }
    }
    if (t < 32) {
        int s = 0;
        #pragma unroll
        for (int pc = 0; pc < NUM_CAMS; ++pc) s += vld[pc * 32 + t];
        cnt[t] = s * 4;
    }
    __syncthreads();   // ph1-2 scratch dead; S may now overwrite U

    // phase 3: 4 interleaved qi chains per warp, fp16 taps (LDG.64/lane)
    const int wid  = t >> 5;
    const int lane = t & 31;
    const int c0   = lane * 4;

    {
        int n[4];
        float4 acc[4];
        int nmax = 0;
        #pragma unroll
        for (int j = 0; j < 4; ++j) {
            int qi = wid + j * 8;
            n[j]   = cnt[qi];
            acc[j] = make_float4(0.f, 0.f, 0.f, 0.f);
            nmax   = max(nmax, n[j]);
        }
        for (int e = 0; e < nmax; ++e) {
            #pragma unroll
            for (int j = 0; j < 4; ++j) {
                if (e < n[j]) {
                    int qi = wid + j * 8;
                    int   pk = entO[qi * 24 + e];
                    uint2 wp = entW[qi * 24 + e];
                    int lvl  = (pk >> 2) & 3;
                    int dx   = (pk & 1) << 7;
                    int dy   = (pk & 2) ? (11264 >> lvl) : 0;
                    const __half* fb = g_feat + (pk & ~127) + c0;
                    uint2 r0 = *(const uint2*)(fb);
                    uint2 r1 = *(const uint2*)(fb + dx);
                    uint2 r2 = *(const uint2*)(fb + dy);
                    uint2 r3 = *(const uint2*)(fb + dy + dx);
                    float2 w01 = __half22float2(*(__half2*)&wp.x);
                    float2 w23 = __half22float2(*(__half2*)&wp.y);
                    float2 a0 = __half22float2(*(__half2*)&r0.x);
                    float2 a1 = __half22float2(*(__half2*)&r0.y);
                    float2 b0 = __half22float2(*(__half2*)&r1.x);
                    float2 b1 = __half22float2(*(__half2*)&r1.y);
                    float2 c2 = __half22float2(*(__half2*)&r2.x);
                    float2 c3 = __half22float2(*(__half2*)&r2.y);
                    float2 d0 = __half22float2(*(__half2*)&r3.x);
                    float2 d1 = __half22float2(*(__half2*)&r3.y);
                    acc[j].x = fmaf(w01.x, a0.x, fmaf(w01.y, b0.x,
                               fmaf(w23.x, c2.x, fmaf(w23.y, d0.x, acc[j].x))));
                    acc[j].y = fmaf(w01.x, a0.y, fmaf(w01.y, b0.y,
                               fmaf(w23.x, c2.y, fmaf(w23.y, d0.y, acc[j].y))));
                    acc[j].z = fmaf(w01.x, a1.x, fmaf(w01.y, b1.x,
                               fmaf(w23.x, c3.x, fmaf(w23.y, d1.x, acc[j].z))));
                    acc[j].w = fmaf(w01.x, a1.y, fmaf(w01.y, b1.y,
                               fmaf(w23.x, c3.y, fmaf(w23.y, d1.y, acc[j].w))));
                }
            }
        }
        #pragma unroll
        for (int j = 0; j < 4; ++j) {
            int qi = wid + j * 8;
            S[(c0 + 0) * 33 + qi] = acc[j].x;
            S[(c0 + 1) * 33 + qi] = acc[j].y;
            S[(c0 + 2) * 33 + qi] = acc[j].z;
            S[(c0 + 3) * 33 + qi] = acc[j].w;
        }
    }
    __syncthreads();

    // coalesced RMW: out += sampled (pos written by k_mlp_mma)
    for (int e = t; e < EMBED * 32; e += 256) {
        int cc = e >> 5, qi = e & 31;
        int q = q0 + qi;
        if (q < GQ) {
            int oi = (cc * NP + p) * GQ + q;
            out[oi] += S[cc * 33 + qi];
        }
    }
}

// ---------------------------------------------------------------------------
extern "C" void kernel_launch(void* const* d_in, const int* in_sizes, int n_in,
                              void* d_out, int out_size)
{
    const float* f0  = (const float*)d_in[0];
    const float* f1  = (const float*)d_in[1];
    const float* f2  = (const float*)d_in[2];
    const float* f3  = (const float*)d_in[3];
    const float* ref = (const float*)d_in[4];
    const float* l2i = (const float*)d_in[5];
    const float* w1  = (const float*)d_in[6];
    const float* b1  = (const float*)d_in[7];
    const float* w2  = (const float*)d_in[8];
    const float* b2  = (const float*)d_in[9];
    float* out = (float*)d_out;

    k_transpose<<<2960, dim3(32, 8)>>>(f0, f1, f2, f3, w2);

    cudaFuncSetAttribute(k_mlp_mma, cudaFuncAttributeMaxDynamicSharedMemorySize,
                         K1_SMEM);
    k_mlp_mma<<<K1_GRID, 256, K1_SMEM>>>(ref, w1, b1, b2, out);

    dim3 grid((GQ + 31) / 32, NP);
    k_sample<<<grid, 256>>>(ref, l2i, out);
}